// round 13
// baseline (speedup 1.0000x reference)
#include <cuda_runtime.h>
#include <cuda_bf16.h>
#include <math.h>
#include <stdint.h>

#define B 256
#define D 128
#define T 512
#define H 256
#define C 10
#define N4 1024

// device scratch (no runtime allocation allowed)
__device__ float g_gates[(size_t)B * T * N4];        // [b][t][4H] fp32, 512 MB
__device__ unsigned short g_hhi[2][B * H];           // h bf16 hi, [b][k], dbl-buffered
__device__ unsigned short g_hlo[2][B * H];           // h bf16 lo
__device__ float g_hfin[B * H];                      // final h fp32
__device__ __align__(128) unsigned g_flags[4][32];   // per-(group, producer) step flags

__device__ __forceinline__ float sigf(float x) { return 1.0f / (1.0f + expf(-x)); }

__global__ void reset_kernel() {
    if (threadIdx.x < 128) ((unsigned*)g_flags)[threadIdx.x] = 0u;
}

__device__ __forceinline__ uint32_t smem_u32(const void* p) {
    uint32_t a;
    asm("{ .reg .u64 t; cvta.to.shared.u64 t, %1; cvt.u32.u64 %0, t; }" : "=r"(a) : "l"(p));
    return a;
}
__device__ __forceinline__ void ldmx4(uint32_t& r0, uint32_t& r1, uint32_t& r2,
                                      uint32_t& r3, uint32_t addr) {
    asm volatile("ldmatrix.sync.aligned.m8n8.x4.shared.b16 {%0,%1,%2,%3}, [%4];"
                 : "=r"(r0), "=r"(r1), "=r"(r2), "=r"(r3) : "r"(addr));
}
__device__ __forceinline__ void ldmx4t(uint32_t* r, uint32_t addr) {
    asm volatile("ldmatrix.sync.aligned.m8n8.x4.trans.shared.b16 {%0,%1,%2,%3}, [%4];"
                 : "=r"(r[0]), "=r"(r[1]), "=r"(r[2]), "=r"(r[3]) : "r"(addr));
}
__device__ __forceinline__ void mma16816(float* c,
                                         uint32_t a0, uint32_t a1, uint32_t a2, uint32_t a3,
                                         uint32_t b0, uint32_t b1) {
    asm volatile(
        "mma.sync.aligned.m16n8k16.row.col.f32.bf16.bf16.f32 "
        "{%0,%1,%2,%3}, {%4,%5,%6,%7}, {%8,%9}, {%0,%1,%2,%3};"
        : "+f"(c[0]), "+f"(c[1]), "+f"(c[2]), "+f"(c[3])
        : "r"(a0), "r"(a1), "r"(a2), "r"(a3), "r"(b0), "r"(b1));
}
__device__ __forceinline__ uint32_t pkbf(float x, float y) {
    __nv_bfloat16 a = __float2bfloat16(x), b = __float2bfloat16(y);
    return (uint32_t)reinterpret_cast<unsigned short&>(a) |
           ((uint32_t)reinterpret_cast<unsigned short&>(b) << 16);
}

// ============================== PROJ (mma) ==================================
#define PPITCH 272
#define P_AHI 0
#define P_ALO (128 * PPITCH)
#define P_BHI (2 * 128 * PPITCH)
#define P_BLO (3 * 128 * PPITCH)
#define SMEM_PROJ (4 * 128 * PPITCH)

__global__ __launch_bounds__(256, 1) void projmma_kernel(
    const float* __restrict__ x,
    const float* __restrict__ Wg, const float* __restrict__ Wi,
    const float* __restrict__ Wf, const float* __restrict__ Wo,
    const float* __restrict__ bg, const float* __restrict__ bi,
    const float* __restrict__ bf, const float* __restrict__ bo)
{
    extern __shared__ char psm[];
    const uint32_t sb = smem_u32(psm);

    const int tid = threadIdx.x;
    const int lane = tid & 31;
    const int w = tid >> 5;
    const int wm2 = w & 3;
    const int nq2 = w >> 2;
    const int n0 = blockIdx.x * 128;
    const int m0 = blockIdx.y * 128;
    const int b  = m0 >> 9;
    const int t0 = m0 & 511;
    const int gate = n0 >> 8;
    const int hb = n0 & 255;

    const float* W    = (gate == 0) ? Wg : (gate == 1) ? Wi : (gate == 2) ? Wf : Wo;
    const float* bias = (gate == 0) ? bg : (gate == 1) ? bi : (gate == 2) ? bf : bo;

    #pragma unroll
    for (int i = 0; i < 16; i++) {
        int q = tid + i * 256;
        int k = q >> 5;
        int m4 = q & 31;
        float4 v = __ldcg(reinterpret_cast<const float4*>(
            &x[(size_t)b * (D * T) + k * T + t0 + m4 * 4]));
        float4 wv = __ldg(reinterpret_cast<const float4*>(&W[k * H + hb + m4 * 4]));
        uint32_t hiA0 = pkbf(v.x, v.y), hiA1 = pkbf(v.z, v.w);
        float rx = v.x - __bfloat162float(__float2bfloat16(v.x));
        float ry = v.y - __bfloat162float(__float2bfloat16(v.y));
        float rz = v.z - __bfloat162float(__float2bfloat16(v.z));
        float rw = v.w - __bfloat162float(__float2bfloat16(v.w));
        uint32_t loA0 = pkbf(rx, ry), loA1 = pkbf(rz, rw);
        uint32_t hiB0 = pkbf(wv.x, wv.y), hiB1 = pkbf(wv.z, wv.w);
        float sx = wv.x - __bfloat162float(__float2bfloat16(wv.x));
        float sy = wv.y - __bfloat162float(__float2bfloat16(wv.y));
        float sz = wv.z - __bfloat162float(__float2bfloat16(wv.z));
        float sw = wv.w - __bfloat162float(__float2bfloat16(wv.w));
        uint32_t loB0 = pkbf(sx, sy), loB1 = pkbf(sz, sw);
        uint32_t off = k * PPITCH + m4 * 8;
        *reinterpret_cast<uint2*>(psm + P_AHI + off) = make_uint2(hiA0, hiA1);
        *reinterpret_cast<uint2*>(psm + P_ALO + off) = make_uint2(loA0, loA1);
        *reinterpret_cast<uint2*>(psm + P_BHI + off) = make_uint2(hiB0, hiB1);
        *reinterpret_cast<uint2*>(psm + P_BLO + off) = make_uint2(loB0, loB1);
    }
    __syncthreads();

    const int sel = lane >> 3;
    const int lr  = lane & 7;
    const uint32_t aoff = (uint32_t)(((sel >> 1) * 8 + lr) * PPITCH + (sel & 1) * 16);
    const uint32_t boff = (uint32_t)(((sel & 1) * 8 + lr) * PPITCH + (sel >> 1) * 16);

    float acc[2][8][4] = {};

    #pragma unroll
    for (int kk = 0; kk < 8; kk++) {
        const uint32_t kb = kk * 16 * PPITCH;
        uint32_t ah[2][4], al[2][4], bh[4][4], bl[4][4];
        #pragma unroll
        for (int mf = 0; mf < 2; mf++) {
            uint32_t mcol = (wm2 * 32 + mf * 16) * 2;
            ldmx4t(ah[mf], sb + P_AHI + kb + aoff + mcol);
            ldmx4t(al[mf], sb + P_ALO + kb + aoff + mcol);
        }
        #pragma unroll
        for (int ng = 0; ng < 4; ng++) {
            uint32_t ncol = (nq2 * 64 + ng * 16) * 2;
            ldmx4t(bh[ng], sb + P_BHI + kb + boff + ncol);
            ldmx4t(bl[ng], sb + P_BLO + kb + boff + ncol);
        }
        #pragma unroll
        for (int mf = 0; mf < 2; mf++) {
            #pragma unroll
            for (int ng = 0; ng < 4; ng++) {
                float* c0 = acc[mf][ng * 2];
                float* c1 = acc[mf][ng * 2 + 1];
                mma16816(c0, ah[mf][0], ah[mf][1], ah[mf][2], ah[mf][3], bh[ng][0], bh[ng][1]);
                mma16816(c0, al[mf][0], al[mf][1], al[mf][2], al[mf][3], bh[ng][0], bh[ng][1]);
                mma16816(c0, ah[mf][0], ah[mf][1], ah[mf][2], ah[mf][3], bl[ng][0], bl[ng][1]);
                mma16816(c1, ah[mf][0], ah[mf][1], ah[mf][2], ah[mf][3], bh[ng][2], bh[ng][3]);
                mma16816(c1, al[mf][0], al[mf][1], al[mf][2], al[mf][3], bh[ng][2], bh[ng][3]);
                mma16816(c1, ah[mf][0], ah[mf][1], ah[mf][2], ah[mf][3], bl[ng][2], bl[ng][3]);
            }
        }
    }

    #pragma unroll
    for (int mf = 0; mf < 2; mf++) {
        int m = m0 + wm2 * 32 + mf * 16 + (lane >> 2);
        #pragma unroll
        for (int j = 0; j < 8; j++) {
            int hcol = hb + nq2 * 64 + j * 8 + (lane & 3) * 2;
            float2 bv = *reinterpret_cast<const float2*>(&bias[hcol]);
            int ncol = gate * 256 + hcol;
            *reinterpret_cast<float2*>(&g_gates[(size_t)m * N4 + ncol]) =
                make_float2(acc[mf][j][0] + bv.x, acc[mf][j][1] + bv.y);
            *reinterpret_cast<float2*>(&g_gates[(size_t)(m + 8) * N4 + ncol]) =
                make_float2(acc[mf][j][2] + bv.x, acc[mf][j][3] + bv.y);
        }
    }
}

// ============================ RECURRENCE ====================================
#define APITCHB 528
#define OFF_AHI 0
#define OFF_ALO (OFF_AHI + 64 * APITCHB)
#define OFF_BHI (OFF_ALO + 64 * APITCHB)
#define OFF_BLO (OFF_BHI + 32 * APITCHB)
#define OFF_CX  (OFF_BLO + 32 * APITCHB)
#define CXP 34
#define SMEM_LSTM (OFF_CX + 64 * CXP * 4)

__global__ __launch_bounds__(256, 1) void lstm_kernel(
    const float* __restrict__ Wg, const float* __restrict__ Wi,
    const float* __restrict__ Wf, const float* __restrict__ Wo)
{
    extern __shared__ char sm[];
    const uint32_t sb = smem_u32(sm);
    float* Cx = reinterpret_cast<float*>(sm + OFF_CX);

    const int tid = threadIdx.x;
    const int lane = tid & 31;
    const int w = tid >> 5;
    const int wm = w & 3;
    const int nq = w >> 2;
    const int nb = blockIdx.x;        // producer id in group (0..31)
    const int gm = blockIdx.y;        // batch group (0..3)
    const int hb8 = nb * 8;

    // Build W tile bf16 hi/lo in smem once: B[n][k], n = g*8+hl
    for (int idx = tid; idx < 32 * 256; idx += 256) {
        int k = idx >> 5;
        int n = idx & 31;
        int g = n >> 3, hl = n & 7;
        const float* W = (g == 0) ? Wg : (g == 1) ? Wi : (g == 2) ? Wf : Wo;
        float wv = W[k * H + hb8 + hl];
        __nv_bfloat16 bh = __float2bfloat16(wv);
        __nv_bfloat16 bl = __float2bfloat16(wv - __bfloat162float(bh));
        *reinterpret_cast<unsigned short*>(sm + OFF_BHI + n * APITCHB + k * 2) =
            reinterpret_cast<unsigned short&>(bh);
        *reinterpret_cast<unsigned short*>(sm + OFF_BLO + n * APITCHB + k * 2) =
            reinterpret_cast<unsigned short&>(bl);
    }
    __syncthreads();

    const uint32_t a_row = wm * 16 + (lane & 7) + ((lane >> 3) & 1) * 8;
    const uint32_t a_base = a_row * APITCHB + (lane >> 4) * 16;
    const uint32_t b_row = nq * 16 + (lane >> 4) * 8 + (lane & 7);
    const uint32_t b_base = b_row * APITCHB + ((lane >> 3) & 1) * 16;

    const int bl_ = tid >> 2;
    const int hl2 = (tid & 3) * 2;
    const int bglob = gm * 64 + bl_;

    unsigned* flags = &g_flags[gm][0];

    float2 cstate = make_float2(0.f, 0.f);

    for (int t = 0; t < T; t++) {
        float2 pg, pi_, pf_, po;
        {
            const size_t rb = ((size_t)bglob * T + t) * N4 + hb8 + hl2;
            pg  = __ldcg(reinterpret_cast<const float2*>(&g_gates[rb]));
            pi_ = __ldcg(reinterpret_cast<const float2*>(&g_gates[rb + 256]));
            pf_ = __ldcg(reinterpret_cast<const float2*>(&g_gates[rb + 512]));
            po  = __ldcg(reinterpret_cast<const float2*>(&g_gates[rb + 768]));
        }

        float2 ag = make_float2(0.f, 0.f), ai = ag, af = ag, ao = ag;

        if (t > 0) {
            // single-thread poll of the 32-flag cache line (no atomic RMW)
            if (tid == 0) {
                unsigned need = (unsigned)t;
                for (;;) {
                    uint4 f0, f1, f2, f3, f4, f5, f6, f7;
                    asm volatile("ld.volatile.global.v4.u32 {%0,%1,%2,%3}, [%4];"
                                 : "=r"(f0.x), "=r"(f0.y), "=r"(f0.z), "=r"(f0.w)
                                 : "l"(flags));
                    asm volatile("ld.volatile.global.v4.u32 {%0,%1,%2,%3}, [%4];"
                                 : "=r"(f1.x), "=r"(f1.y), "=r"(f1.z), "=r"(f1.w)
                                 : "l"(flags + 4));
                    asm volatile("ld.volatile.global.v4.u32 {%0,%1,%2,%3}, [%4];"
                                 : "=r"(f2.x), "=r"(f2.y), "=r"(f2.z), "=r"(f2.w)
                                 : "l"(flags + 8));
                    asm volatile("ld.volatile.global.v4.u32 {%0,%1,%2,%3}, [%4];"
                                 : "=r"(f3.x), "=r"(f3.y), "=r"(f3.z), "=r"(f3.w)
                                 : "l"(flags + 12));
                    asm volatile("ld.volatile.global.v4.u32 {%0,%1,%2,%3}, [%4];"
                                 : "=r"(f4.x), "=r"(f4.y), "=r"(f4.z), "=r"(f4.w)
                                 : "l"(flags + 16));
                    asm volatile("ld.volatile.global.v4.u32 {%0,%1,%2,%3}, [%4];"
                                 : "=r"(f5.x), "=r"(f5.y), "=r"(f5.z), "=r"(f5.w)
                                 : "l"(flags + 20));
                    asm volatile("ld.volatile.global.v4.u32 {%0,%1,%2,%3}, [%4];"
                                 : "=r"(f6.x), "=r"(f6.y), "=r"(f6.z), "=r"(f6.w)
                                 : "l"(flags + 24));
                    asm volatile("ld.volatile.global.v4.u32 {%0,%1,%2,%3}, [%4];"
                                 : "=r"(f7.x), "=r"(f7.y), "=r"(f7.z), "=r"(f7.w)
                                 : "l"(flags + 28));
                    unsigned mn = f0.x;
                    mn = min(mn, f0.y); mn = min(mn, f0.z); mn = min(mn, f0.w);
                    mn = min(mn, f1.x); mn = min(mn, f1.y); mn = min(mn, f1.z); mn = min(mn, f1.w);
                    mn = min(mn, f2.x); mn = min(mn, f2.y); mn = min(mn, f2.z); mn = min(mn, f2.w);
                    mn = min(mn, f3.x); mn = min(mn, f3.y); mn = min(mn, f3.z); mn = min(mn, f3.w);
                    mn = min(mn, f4.x); mn = min(mn, f4.y); mn = min(mn, f4.z); mn = min(mn, f4.w);
                    mn = min(mn, f5.x); mn = min(mn, f5.y); mn = min(mn, f5.z); mn = min(mn, f5.w);
                    mn = min(mn, f6.x); mn = min(mn, f6.y); mn = min(mn, f6.z); mn = min(mn, f6.w);
                    mn = min(mn, f7.x); mn = min(mn, f7.y); mn = min(mn, f7.z); mn = min(mn, f7.w);
                    if (mn >= need) break;
                }
                asm volatile("fence.acq_rel.gpu;" ::: "memory");
            }
            __syncthreads();                    // BAR: h(t-1) visible to CTA

            const unsigned short* src_hi = g_hhi[(t + 1) & 1];
            const unsigned short* src_lo = g_hlo[(t + 1) & 1];
            #pragma unroll
            for (int i = 0; i < 8; i++) {
                int idx = tid + i * 256;
                int m = idx >> 5;
                int ch = idx & 31;
                size_t gidx = (size_t)(gm * 64 + m) * H + ch * 8;
                uint4 vh = __ldcg(reinterpret_cast<const uint4*>(&src_hi[gidx]));
                uint4 vl = __ldcg(reinterpret_cast<const uint4*>(&src_lo[gidx]));
                *reinterpret_cast<uint4*>(sm + OFF_AHI + m * APITCHB + ch * 16) = vh;
                *reinterpret_cast<uint4*>(sm + OFF_ALO + m * APITCHB + ch * 16) = vl;
            }
            __syncthreads();                    // BAR: A tile staged

            float c0[4] = {0.f, 0.f, 0.f, 0.f};
            float c1[4] = {0.f, 0.f, 0.f, 0.f};
            #pragma unroll
            for (int kk = 0; kk < 16; kk++) {
                uint32_t ah[4], al[4], bh[4], blx[4];
                ldmx4(ah[0], ah[1], ah[2], ah[3], sb + OFF_AHI + a_base + kk * 32);
                ldmx4(al[0], al[1], al[2], al[3], sb + OFF_ALO + a_base + kk * 32);
                ldmx4(bh[0], bh[1], bh[2], bh[3], sb + OFF_BHI + b_base + kk * 32);
                ldmx4(blx[0], blx[1], blx[2], blx[3], sb + OFF_BLO + b_base + kk * 32);
                mma16816(c0, ah[0], ah[1], ah[2], ah[3], bh[0], bh[1]);
                mma16816(c0, al[0], al[1], al[2], al[3], bh[0], bh[1]);
                mma16816(c0, ah[0], ah[1], ah[2], ah[3], blx[0], blx[1]);
                mma16816(c1, ah[0], ah[1], ah[2], ah[3], bh[2], bh[3]);
                mma16816(c1, al[0], al[1], al[2], al[3], bh[2], bh[3]);
                mma16816(c1, ah[0], ah[1], ah[2], ah[3], blx[2], blx[3]);
            }

            {
                int crow = wm * 16 + (lane >> 2);
                int ccol = nq * 16 + (lane & 3) * 2;
                *reinterpret_cast<float2*>(&Cx[crow * CXP + ccol]) = make_float2(c0[0], c0[1]);
                *reinterpret_cast<float2*>(&Cx[(crow + 8) * CXP + ccol]) = make_float2(c0[2], c0[3]);
                *reinterpret_cast<float2*>(&Cx[crow * CXP + ccol + 8]) = make_float2(c1[0], c1[1]);
                *reinterpret_cast<float2*>(&Cx[(crow + 8) * CXP + ccol + 8]) = make_float2(c1[2], c1[3]);
            }
            __syncthreads();                    // BAR: C exchange ready

            ag = *reinterpret_cast<float2*>(&Cx[bl_ * CXP + 0 * 8 + hl2]);
            ai = *reinterpret_cast<float2*>(&Cx[bl_ * CXP + 1 * 8 + hl2]);
            af = *reinterpret_cast<float2*>(&Cx[bl_ * CXP + 2 * 8 + hl2]);
            ao = *reinterpret_cast<float2*>(&Cx[bl_ * CXP + 3 * 8 + hl2]);
        }

        float hx = tanhf(pg.x + ag.x);
        float hy = tanhf(pg.y + ag.y);
        float ix = sigf(pi_.x + ai.x);
        float iy = sigf(pi_.y + ai.y);
        float fx = sigf(pf_.x + af.x);
        float fy = sigf(pf_.y + af.y);
        float ox = sigf(po.x + ao.x);
        float oy = sigf(po.y + ao.y);
        cstate.x = hx * ix + cstate.x * fx;
        cstate.y = hy * iy + cstate.y * fy;
        float h0 = tanhf(cstate.x) * ox;
        float h1 = tanhf(cstate.y) * oy;

        if (t < T - 1) {
            unsigned uhi = pkbf(h0, h1);
            __nv_bfloat16 q0 = __float2bfloat16(h0);
            __nv_bfloat16 q1 = __float2bfloat16(h1);
            unsigned ulo = pkbf(h0 - __bfloat162float(q0), h1 - __bfloat162float(q1));
            size_t hidx = (size_t)bglob * H + hb8 + hl2;
            __stcg(reinterpret_cast<unsigned*>(&g_hhi[t & 1][hidx]), uhi);
            __stcg(reinterpret_cast<unsigned*>(&g_hlo[t & 1][hidx]), ulo);
            __syncthreads();                    // BAR: all h stores issued
            if (tid == 0) {
                asm volatile("st.release.gpu.global.u32 [%0], %1;"
                             :: "l"(&flags[nb]), "r"((unsigned)(t + 1)) : "memory");
            }
        } else {
            *reinterpret_cast<float2*>(&g_hfin[(size_t)bglob * H + hb8 + hl2]) =
                make_float2(h0, h1);
        }
    }
}

// ================================ HEAD ======================================
__global__ void final_kernel(const float* __restrict__ Wp,
                             const float* __restrict__ bp,
                             float* __restrict__ out)
{
    __shared__ float hsm[H];
    int b = blockIdx.x;
    hsm[threadIdx.x] = g_hfin[b * H + threadIdx.x];
    __syncthreads();
    if (threadIdx.x < C) {
        float acc = bp[threadIdx.x];
        #pragma unroll 8
        for (int k = 0; k < H; k++)
            acc += hsm[k] * Wp[k * C + threadIdx.x];
        out[b * C + threadIdx.x] = acc;
    }
}

// ---------------------------------------------------------------------------
extern "C" void kernel_launch(void* const* d_in, const int* in_sizes, int n_in,
                              void* d_out, int out_size)
{
    const float* x    = (const float*)d_in[0];
    const float* W_gx = (const float*)d_in[1];
    const float* W_ix = (const float*)d_in[2];
    const float* W_fx = (const float*)d_in[3];
    const float* W_ox = (const float*)d_in[4];
    const float* W_gh = (const float*)d_in[5];
    const float* W_ih = (const float*)d_in[6];
    const float* W_fh = (const float*)d_in[7];
    const float* W_oh = (const float*)d_in[8];
    const float* b_g  = (const float*)d_in[9];
    const float* b_i  = (const float*)d_in[10];
    const float* b_f  = (const float*)d_in[11];
    const float* b_o  = (const float*)d_in[12];
    const float* W_ph = (const float*)d_in[13];
    const float* b_p  = (const float*)d_in[14];
    float* out = (float*)d_out;

    static bool attr_set = false;
    if (!attr_set) {
        cudaFuncSetAttribute(lstm_kernel,
                             cudaFuncAttributeMaxDynamicSharedMemorySize, SMEM_LSTM);
        cudaFuncSetAttribute(projmma_kernel,
                             cudaFuncAttributeMaxDynamicSharedMemorySize, SMEM_PROJ);
        attr_set = true;
    }

    reset_kernel<<<1, 128>>>();

    projmma_kernel<<<dim3(N4 / 128, (B * T) / 128), 256, SMEM_PROJ>>>(
        x, W_gx, W_ix, W_fx, W_ox, b_g, b_i, b_f, b_o);

    lstm_kernel<<<dim3(32, 4), 256, SMEM_LSTM>>>(W_gh, W_ih, W_fh, W_oh);

    final_kernel<<<B, H>>>(W_ph, b_p, out);
}

// round 14
// speedup vs baseline: 1.5074x; 1.5074x over previous
#include <cuda_runtime.h>
#include <cuda_bf16.h>
#include <math.h>
#include <stdint.h>

#define B 256
#define D 128
#define T 512
#define H 256
#define C 10
#define N4 1024

// device scratch (no runtime allocation allowed)
__device__ float g_gates[(size_t)B * T * N4];        // [b][t][4H] fp32, 512 MB
__device__ unsigned short g_hhi[2][B * H];           // h bf16 hi, [b][k], dbl-buffered
__device__ unsigned short g_hlo[2][B * H];           // h bf16 lo
__device__ float g_hfin[B * H];                      // final h fp32
__device__ unsigned g_bar4[4];                       // per-group step counters

// fast activations: __expf-based (rel err ~1e-6, saturating, no NaN)
__device__ __forceinline__ float sigf(float x) { return 1.0f / (1.0f + __expf(-x)); }
__device__ __forceinline__ float tanf_(float x) {
    float e = __expf(2.0f * x);
    return 1.0f - 2.0f / (e + 1.0f);
}

__global__ void reset_kernel() {
    if (threadIdx.x < 4) g_bar4[threadIdx.x] = 0u;
}

__device__ __forceinline__ uint32_t smem_u32(const void* p) {
    uint32_t a;
    asm("{ .reg .u64 t; cvta.to.shared.u64 t, %1; cvt.u32.u64 %0, t; }" : "=r"(a) : "l"(p));
    return a;
}
__device__ __forceinline__ void ldmx4(uint32_t& r0, uint32_t& r1, uint32_t& r2,
                                      uint32_t& r3, uint32_t addr) {
    asm volatile("ldmatrix.sync.aligned.m8n8.x4.shared.b16 {%0,%1,%2,%3}, [%4];"
                 : "=r"(r0), "=r"(r1), "=r"(r2), "=r"(r3) : "r"(addr));
}
__device__ __forceinline__ void ldmx4t(uint32_t* r, uint32_t addr) {
    asm volatile("ldmatrix.sync.aligned.m8n8.x4.trans.shared.b16 {%0,%1,%2,%3}, [%4];"
                 : "=r"(r[0]), "=r"(r[1]), "=r"(r[2]), "=r"(r[3]) : "r"(addr));
}
__device__ __forceinline__ void mma16816(float* c,
                                         uint32_t a0, uint32_t a1, uint32_t a2, uint32_t a3,
                                         uint32_t b0, uint32_t b1) {
    asm volatile(
        "mma.sync.aligned.m16n8k16.row.col.f32.bf16.bf16.f32 "
        "{%0,%1,%2,%3}, {%4,%5,%6,%7}, {%8,%9}, {%0,%1,%2,%3};"
        : "+f"(c[0]), "+f"(c[1]), "+f"(c[2]), "+f"(c[3])
        : "r"(a0), "r"(a1), "r"(a2), "r"(a3), "r"(b0), "r"(b1));
}
__device__ __forceinline__ uint32_t pkbf(float x, float y) {
    __nv_bfloat16 a = __float2bfloat16(x), b = __float2bfloat16(y);
    return (uint32_t)reinterpret_cast<unsigned short&>(a) |
           ((uint32_t)reinterpret_cast<unsigned short&>(b) << 16);
}

// ============================== PROJ (mma) ==================================
#define PPITCH 272
#define P_AHI 0
#define P_ALO (128 * PPITCH)
#define P_BHI (2 * 128 * PPITCH)
#define P_BLO (3 * 128 * PPITCH)
#define SMEM_PROJ (4 * 128 * PPITCH)

__global__ __launch_bounds__(256, 1) void projmma_kernel(
    const float* __restrict__ x,
    const float* __restrict__ Wg, const float* __restrict__ Wi,
    const float* __restrict__ Wf, const float* __restrict__ Wo,
    const float* __restrict__ bg, const float* __restrict__ bi,
    const float* __restrict__ bf, const float* __restrict__ bo)
{
    extern __shared__ char psm[];
    const uint32_t sb = smem_u32(psm);

    const int tid = threadIdx.x;
    const int lane = tid & 31;
    const int w = tid >> 5;
    const int wm2 = w & 3;
    const int nq2 = w >> 2;
    const int n0 = blockIdx.x * 128;
    const int m0 = blockIdx.y * 128;
    const int b  = m0 >> 9;
    const int t0 = m0 & 511;
    const int gate = n0 >> 8;
    const int hb = n0 & 255;

    const float* W    = (gate == 0) ? Wg : (gate == 1) ? Wi : (gate == 2) ? Wf : Wo;
    const float* bias = (gate == 0) ? bg : (gate == 1) ? bi : (gate == 2) ? bf : bo;

    #pragma unroll
    for (int i = 0; i < 16; i++) {
        int q = tid + i * 256;
        int k = q >> 5;
        int m4 = q & 31;
        float4 v = __ldcg(reinterpret_cast<const float4*>(
            &x[(size_t)b * (D * T) + k * T + t0 + m4 * 4]));
        float4 wv = __ldg(reinterpret_cast<const float4*>(&W[k * H + hb + m4 * 4]));
        uint32_t hiA0 = pkbf(v.x, v.y), hiA1 = pkbf(v.z, v.w);
        float rx = v.x - __bfloat162float(__float2bfloat16(v.x));
        float ry = v.y - __bfloat162float(__float2bfloat16(v.y));
        float rz = v.z - __bfloat162float(__float2bfloat16(v.z));
        float rw = v.w - __bfloat162float(__float2bfloat16(v.w));
        uint32_t loA0 = pkbf(rx, ry), loA1 = pkbf(rz, rw);
        uint32_t hiB0 = pkbf(wv.x, wv.y), hiB1 = pkbf(wv.z, wv.w);
        float sx = wv.x - __bfloat162float(__float2bfloat16(wv.x));
        float sy = wv.y - __bfloat162float(__float2bfloat16(wv.y));
        float sz = wv.z - __bfloat162float(__float2bfloat16(wv.z));
        float sw = wv.w - __bfloat162float(__float2bfloat16(wv.w));
        uint32_t loB0 = pkbf(sx, sy), loB1 = pkbf(sz, sw);
        uint32_t off = k * PPITCH + m4 * 8;
        *reinterpret_cast<uint2*>(psm + P_AHI + off) = make_uint2(hiA0, hiA1);
        *reinterpret_cast<uint2*>(psm + P_ALO + off) = make_uint2(loA0, loA1);
        *reinterpret_cast<uint2*>(psm + P_BHI + off) = make_uint2(hiB0, hiB1);
        *reinterpret_cast<uint2*>(psm + P_BLO + off) = make_uint2(loB0, loB1);
    }
    __syncthreads();

    const int sel = lane >> 3;
    const int lr  = lane & 7;
    const uint32_t aoff = (uint32_t)(((sel >> 1) * 8 + lr) * PPITCH + (sel & 1) * 16);
    const uint32_t boff = (uint32_t)(((sel & 1) * 8 + lr) * PPITCH + (sel >> 1) * 16);

    float acc[2][8][4] = {};

    #pragma unroll
    for (int kk = 0; kk < 8; kk++) {
        const uint32_t kb = kk * 16 * PPITCH;
        uint32_t ah[2][4], al[2][4], bh[4][4], bl[4][4];
        #pragma unroll
        for (int mf = 0; mf < 2; mf++) {
            uint32_t mcol = (wm2 * 32 + mf * 16) * 2;
            ldmx4t(ah[mf], sb + P_AHI + kb + aoff + mcol);
            ldmx4t(al[mf], sb + P_ALO + kb + aoff + mcol);
        }
        #pragma unroll
        for (int ng = 0; ng < 4; ng++) {
            uint32_t ncol = (nq2 * 64 + ng * 16) * 2;
            ldmx4t(bh[ng], sb + P_BHI + kb + boff + ncol);
            ldmx4t(bl[ng], sb + P_BLO + kb + boff + ncol);
        }
        #pragma unroll
        for (int mf = 0; mf < 2; mf++) {
            #pragma unroll
            for (int ng = 0; ng < 4; ng++) {
                float* c0 = acc[mf][ng * 2];
                float* c1 = acc[mf][ng * 2 + 1];
                mma16816(c0, ah[mf][0], ah[mf][1], ah[mf][2], ah[mf][3], bh[ng][0], bh[ng][1]);
                mma16816(c0, al[mf][0], al[mf][1], al[mf][2], al[mf][3], bh[ng][0], bh[ng][1]);
                mma16816(c0, ah[mf][0], ah[mf][1], ah[mf][2], ah[mf][3], bl[ng][0], bl[ng][1]);
                mma16816(c1, ah[mf][0], ah[mf][1], ah[mf][2], ah[mf][3], bh[ng][2], bh[ng][3]);
                mma16816(c1, al[mf][0], al[mf][1], al[mf][2], al[mf][3], bh[ng][2], bh[ng][3]);
                mma16816(c1, ah[mf][0], ah[mf][1], ah[mf][2], ah[mf][3], bl[ng][2], bl[ng][3]);
            }
        }
    }

    #pragma unroll
    for (int mf = 0; mf < 2; mf++) {
        int m = m0 + wm2 * 32 + mf * 16 + (lane >> 2);
        #pragma unroll
        for (int j = 0; j < 8; j++) {
            int hcol = hb + nq2 * 64 + j * 8 + (lane & 3) * 2;
            float2 bv = *reinterpret_cast<const float2*>(&bias[hcol]);
            int ncol = gate * 256 + hcol;
            *reinterpret_cast<float2*>(&g_gates[(size_t)m * N4 + ncol]) =
                make_float2(acc[mf][j][0] + bv.x, acc[mf][j][1] + bv.y);
            *reinterpret_cast<float2*>(&g_gates[(size_t)(m + 8) * N4 + ncol]) =
                make_float2(acc[mf][j][2] + bv.x, acc[mf][j][3] + bv.y);
        }
    }
}

// ============================ RECURRENCE ====================================
#define APITCHB 528
#define OFF_AHI 0
#define OFF_ALO (OFF_AHI + 64 * APITCHB)
#define OFF_BHI (OFF_ALO + 64 * APITCHB)
#define OFF_BLO (OFF_BHI + 32 * APITCHB)
#define OFF_CX  (OFF_BLO + 32 * APITCHB)
#define CXP 34
#define SMEM_LSTM (OFF_CX + 64 * CXP * 4)

__global__ __launch_bounds__(256, 1) void lstm_kernel(
    const float* __restrict__ Wg, const float* __restrict__ Wi,
    const float* __restrict__ Wf, const float* __restrict__ Wo)
{
    extern __shared__ char sm[];
    const uint32_t sb = smem_u32(sm);
    float* Cx = reinterpret_cast<float*>(sm + OFF_CX);

    const int tid = threadIdx.x;
    const int lane = tid & 31;
    const int w = tid >> 5;
    const int wm = w & 3;
    const int nq = w >> 2;
    const int nb = blockIdx.x;        // producer id in group (0..31)
    const int gm = blockIdx.y;        // batch group (0..3)
    const int hb8 = nb * 8;

    // Build W tile bf16 hi/lo in smem once: B[n][k], n = g*8+hl
    for (int idx = tid; idx < 32 * 256; idx += 256) {
        int k = idx >> 5;
        int n = idx & 31;
        int g = n >> 3, hl = n & 7;
        const float* W = (g == 0) ? Wg : (g == 1) ? Wi : (g == 2) ? Wf : Wo;
        float wv = W[k * H + hb8 + hl];
        __nv_bfloat16 bh = __float2bfloat16(wv);
        __nv_bfloat16 bl = __float2bfloat16(wv - __bfloat162float(bh));
        *reinterpret_cast<unsigned short*>(sm + OFF_BHI + n * APITCHB + k * 2) =
            reinterpret_cast<unsigned short&>(bh);
        *reinterpret_cast<unsigned short*>(sm + OFF_BLO + n * APITCHB + k * 2) =
            reinterpret_cast<unsigned short&>(bl);
    }
    __syncthreads();

    const uint32_t a_row = wm * 16 + (lane & 7) + ((lane >> 3) & 1) * 8;
    const uint32_t a_base = a_row * APITCHB + (lane >> 4) * 16;
    const uint32_t b_row = nq * 16 + (lane >> 4) * 8 + (lane & 7);
    const uint32_t b_base = b_row * APITCHB + ((lane >> 3) & 1) * 16;

    const int bl_ = tid >> 2;
    const int hl2 = (tid & 3) * 2;
    const int bglob = gm * 64 + bl_;

    float2 cstate = make_float2(0.f, 0.f);

    for (int t = 0; t < T; t++) {
        // gate pre-activations (independent of h) — issue before the wait
        float2 pg, pi_, pf_, po;
        {
            const size_t rb = ((size_t)bglob * T + t) * N4 + hb8 + hl2;
            pg  = __ldcg(reinterpret_cast<const float2*>(&g_gates[rb]));
            pi_ = __ldcg(reinterpret_cast<const float2*>(&g_gates[rb + 256]));
            pf_ = __ldcg(reinterpret_cast<const float2*>(&g_gates[rb + 512]));
            po  = __ldcg(reinterpret_cast<const float2*>(&g_gates[rb + 768]));
        }

        float2 ag = make_float2(0.f, 0.f), ai = ag, af = ag, ao = ag;

        if (t > 0) {
            // warp-autonomous poll: every warp waits on the group counter
            // (all lanes load the same word -> one broadcast request/warp);
            // each warp's acquire orders its subsequent h loads. No BARs here.
            {
                unsigned need = 32u * (unsigned)t;
                unsigned v;
                do {
                    asm volatile("ld.acquire.gpu.global.u32 %0, [%1];"
                                 : "=r"(v) : "l"(&g_bar4[gm]) : "memory");
                } while (v < need);
            }

            const unsigned short* src_hi = g_hhi[(t + 1) & 1];
            const unsigned short* src_lo = g_hlo[(t + 1) & 1];
            #pragma unroll
            for (int i = 0; i < 8; i++) {
                int idx = tid + i * 256;
                int m = idx >> 5;
                int ch = idx & 31;
                size_t gidx = (size_t)(gm * 64 + m) * H + ch * 8;
                uint4 vh = __ldcg(reinterpret_cast<const uint4*>(&src_hi[gidx]));
                uint4 vl = __ldcg(reinterpret_cast<const uint4*>(&src_lo[gidx]));
                *reinterpret_cast<uint4*>(sm + OFF_AHI + m * APITCHB + ch * 16) = vh;
                *reinterpret_cast<uint4*>(sm + OFF_ALO + m * APITCHB + ch * 16) = vl;
            }
            __syncthreads();                    // BAR 1: A tile staged

            float c0[4] = {0.f, 0.f, 0.f, 0.f};
            float c1[4] = {0.f, 0.f, 0.f, 0.f};
            #pragma unroll
            for (int kk = 0; kk < 16; kk++) {
                uint32_t ah[4], al[4], bh[4], blx[4];
                ldmx4(ah[0], ah[1], ah[2], ah[3], sb + OFF_AHI + a_base + kk * 32);
                ldmx4(al[0], al[1], al[2], al[3], sb + OFF_ALO + a_base + kk * 32);
                ldmx4(bh[0], bh[1], bh[2], bh[3], sb + OFF_BHI + b_base + kk * 32);
                ldmx4(blx[0], blx[1], blx[2], blx[3], sb + OFF_BLO + b_base + kk * 32);
                mma16816(c0, ah[0], ah[1], ah[2], ah[3], bh[0], bh[1]);
                mma16816(c0, al[0], al[1], al[2], al[3], bh[0], bh[1]);
                mma16816(c0, ah[0], ah[1], ah[2], ah[3], blx[0], blx[1]);
                mma16816(c1, ah[0], ah[1], ah[2], ah[3], bh[2], bh[3]);
                mma16816(c1, al[0], al[1], al[2], al[3], bh[2], bh[3]);
                mma16816(c1, ah[0], ah[1], ah[2], ah[3], blx[2], blx[3]);
            }

            {
                int crow = wm * 16 + (lane >> 2);
                int ccol = nq * 16 + (lane & 3) * 2;
                *reinterpret_cast<float2*>(&Cx[crow * CXP + ccol]) = make_float2(c0[0], c0[1]);
                *reinterpret_cast<float2*>(&Cx[(crow + 8) * CXP + ccol]) = make_float2(c0[2], c0[3]);
                *reinterpret_cast<float2*>(&Cx[crow * CXP + ccol + 8]) = make_float2(c1[0], c1[1]);
                *reinterpret_cast<float2*>(&Cx[(crow + 8) * CXP + ccol + 8]) = make_float2(c1[2], c1[3]);
            }
            __syncthreads();                    // BAR 2: C exchange ready

            ag = *reinterpret_cast<float2*>(&Cx[bl_ * CXP + 0 * 8 + hl2]);
            ai = *reinterpret_cast<float2*>(&Cx[bl_ * CXP + 1 * 8 + hl2]);
            af = *reinterpret_cast<float2*>(&Cx[bl_ * CXP + 2 * 8 + hl2]);
            ao = *reinterpret_cast<float2*>(&Cx[bl_ * CXP + 3 * 8 + hl2]);
        }

        float hx = tanf_(pg.x + ag.x);
        float hy = tanf_(pg.y + ag.y);
        float ix = sigf(pi_.x + ai.x);
        float iy = sigf(pi_.y + ai.y);
        float fx = sigf(pf_.x + af.x);
        float fy = sigf(pf_.y + af.y);
        float ox = sigf(po.x + ao.x);
        float oy = sigf(po.y + ao.y);
        cstate.x = hx * ix + cstate.x * fx;
        cstate.y = hy * iy + cstate.y * fy;
        float h0 = tanf_(cstate.x) * ox;
        float h1 = tanf_(cstate.y) * oy;

        if (t < T - 1) {
            unsigned uhi = pkbf(h0, h1);
            __nv_bfloat16 q0 = __float2bfloat16(h0);
            __nv_bfloat16 q1 = __float2bfloat16(h1);
            unsigned ulo = pkbf(h0 - __bfloat162float(q0), h1 - __bfloat162float(q1));
            size_t hidx = (size_t)bglob * H + hb8 + hl2;
            __stcg(reinterpret_cast<unsigned*>(&g_hhi[t & 1][hidx]), uhi);
            __stcg(reinterpret_cast<unsigned*>(&g_hlo[t & 1][hidx]), ulo);
            __syncthreads();                    // BAR 3: all h stores issued
            if (tid == 0) {
                asm volatile("red.release.gpu.global.add.u32 [%0], %1;"
                             :: "l"(&g_bar4[gm]), "r"(1u) : "memory");
            }
        } else {
            *reinterpret_cast<float2*>(&g_hfin[(size_t)bglob * H + hb8 + hl2]) =
                make_float2(h0, h1);
        }
    }
}

// ================================ HEAD ======================================
__global__ void final_kernel(const float* __restrict__ Wp,
                             const float* __restrict__ bp,
                             float* __restrict__ out)
{
    __shared__ float hsm[H];
    int b = blockIdx.x;
    hsm[threadIdx.x] = g_hfin[b * H + threadIdx.x];
    __syncthreads();
    if (threadIdx.x < C) {
        float acc = bp[threadIdx.x];
        #pragma unroll 8
        for (int k = 0; k < H; k++)
            acc += hsm[k] * Wp[k * C + threadIdx.x];
        out[b * C + threadIdx.x] = acc;
    }
}

// ---------------------------------------------------------------------------
extern "C" void kernel_launch(void* const* d_in, const int* in_sizes, int n_in,
                              void* d_out, int out_size)
{
    const float* x    = (const float*)d_in[0];
    const float* W_gx = (const float*)d_in[1];
    const float* W_ix = (const float*)d_in[2];
    const float* W_fx = (const float*)d_in[3];
    const float* W_ox = (const float*)d_in[4];
    const float* W_gh = (const float*)d_in[5];
    const float* W_ih = (const float*)d_in[6];
    const float* W_fh = (const float*)d_in[7];
    const float* W_oh = (const float*)d_in[8];
    const float* b_g  = (const float*)d_in[9];
    const float* b_i  = (const float*)d_in[10];
    const float* b_f  = (const float*)d_in[11];
    const float* b_o  = (const float*)d_in[12];
    const float* W_ph = (const float*)d_in[13];
    const float* b_p  = (const float*)d_in[14];
    float* out = (float*)d_out;

    static bool attr_set = false;
    if (!attr_set) {
        cudaFuncSetAttribute(lstm_kernel,
                             cudaFuncAttributeMaxDynamicSharedMemorySize, SMEM_LSTM);
        cudaFuncSetAttribute(projmma_kernel,
                             cudaFuncAttributeMaxDynamicSharedMemorySize, SMEM_PROJ);
        attr_set = true;
    }

    reset_kernel<<<1, 32>>>();

    projmma_kernel<<<dim3(N4 / 128, (B * T) / 128), 256, SMEM_PROJ>>>(
        x, W_gx, W_ix, W_fx, W_ox, b_g, b_i, b_f, b_o);

    lstm_kernel<<<dim3(32, 4), 256, SMEM_LSTM>>>(W_gh, W_ih, W_fh, W_oh);

    final_kernel<<<B, H>>>(W_ph, b_p, out);
}

// round 15
// speedup vs baseline: 1.7159x; 1.1383x over previous
#include <cuda_runtime.h>
#include <cuda_bf16.h>
#include <math.h>
#include <stdint.h>

#define B 256
#define D 128
#define T 512
#define H 256
#define C 10
#define N4 1024

// device scratch (no runtime allocation allowed)
__device__ float g_gates[(size_t)B * T * N4];        // [b][t][4H] fp32, 512 MB
__device__ unsigned short g_hhi[2][B * H];           // h bf16 hi, [b][k], dbl-buffered
__device__ unsigned short g_hlo[2][B * H];           // h bf16 lo
__device__ float g_hfin[B * H];                      // final h fp32
__device__ unsigned g_bar8[8];                       // per-group step counters

// fast activations: __expf-based (rel err ~1e-6, saturating, no NaN)
__device__ __forceinline__ float sigf(float x) { return 1.0f / (1.0f + __expf(-x)); }
__device__ __forceinline__ float tanf_(float x) {
    float e = __expf(2.0f * x);
    return 1.0f - 2.0f / (e + 1.0f);
}

__global__ void reset_kernel() {
    if (threadIdx.x < 8) g_bar8[threadIdx.x] = 0u;
}

__device__ __forceinline__ uint32_t smem_u32(const void* p) {
    uint32_t a;
    asm("{ .reg .u64 t; cvta.to.shared.u64 t, %1; cvt.u32.u64 %0, t; }" : "=r"(a) : "l"(p));
    return a;
}
__device__ __forceinline__ void ldmx4(uint32_t& r0, uint32_t& r1, uint32_t& r2,
                                      uint32_t& r3, uint32_t addr) {
    asm volatile("ldmatrix.sync.aligned.m8n8.x4.shared.b16 {%0,%1,%2,%3}, [%4];"
                 : "=r"(r0), "=r"(r1), "=r"(r2), "=r"(r3) : "r"(addr));
}
__device__ __forceinline__ void ldmx4t(uint32_t* r, uint32_t addr) {
    asm volatile("ldmatrix.sync.aligned.m8n8.x4.trans.shared.b16 {%0,%1,%2,%3}, [%4];"
                 : "=r"(r[0]), "=r"(r[1]), "=r"(r[2]), "=r"(r[3]) : "r"(addr));
}
__device__ __forceinline__ void mma16816(float* c,
                                         uint32_t a0, uint32_t a1, uint32_t a2, uint32_t a3,
                                         uint32_t b0, uint32_t b1) {
    asm volatile(
        "mma.sync.aligned.m16n8k16.row.col.f32.bf16.bf16.f32 "
        "{%0,%1,%2,%3}, {%4,%5,%6,%7}, {%8,%9}, {%0,%1,%2,%3};"
        : "+f"(c[0]), "+f"(c[1]), "+f"(c[2]), "+f"(c[3])
        : "r"(a0), "r"(a1), "r"(a2), "r"(a3), "r"(b0), "r"(b1));
}
__device__ __forceinline__ uint32_t pkbf(float x, float y) {
    __nv_bfloat16 a = __float2bfloat16(x), b = __float2bfloat16(y);
    return (uint32_t)reinterpret_cast<unsigned short&>(a) |
           ((uint32_t)reinterpret_cast<unsigned short&>(b) << 16);
}

// ============================== PROJ (mma) ==================================
#define PPITCH 272
#define P_AHI 0
#define P_ALO (128 * PPITCH)
#define P_BHI (2 * 128 * PPITCH)
#define P_BLO (3 * 128 * PPITCH)
#define SMEM_PROJ (4 * 128 * PPITCH)

__global__ __launch_bounds__(256, 1) void projmma_kernel(
    const float* __restrict__ x,
    const float* __restrict__ Wg, const float* __restrict__ Wi,
    const float* __restrict__ Wf, const float* __restrict__ Wo,
    const float* __restrict__ bg, const float* __restrict__ bi,
    const float* __restrict__ bf, const float* __restrict__ bo)
{
    extern __shared__ char psm[];
    const uint32_t sb = smem_u32(psm);

    const int tid = threadIdx.x;
    const int lane = tid & 31;
    const int w = tid >> 5;
    const int wm2 = w & 3;
    const int nq2 = w >> 2;
    const int n0 = blockIdx.x * 128;
    const int m0 = blockIdx.y * 128;
    const int b  = m0 >> 9;
    const int t0 = m0 & 511;
    const int gate = n0 >> 8;
    const int hb = n0 & 255;

    const float* W    = (gate == 0) ? Wg : (gate == 1) ? Wi : (gate == 2) ? Wf : Wo;
    const float* bias = (gate == 0) ? bg : (gate == 1) ? bi : (gate == 2) ? bf : bo;

    #pragma unroll
    for (int i = 0; i < 16; i++) {
        int q = tid + i * 256;
        int k = q >> 5;
        int m4 = q & 31;
        float4 v = __ldcg(reinterpret_cast<const float4*>(
            &x[(size_t)b * (D * T) + k * T + t0 + m4 * 4]));
        float4 wv = __ldg(reinterpret_cast<const float4*>(&W[k * H + hb + m4 * 4]));
        uint32_t hiA0 = pkbf(v.x, v.y), hiA1 = pkbf(v.z, v.w);
        float rx = v.x - __bfloat162float(__float2bfloat16(v.x));
        float ry = v.y - __bfloat162float(__float2bfloat16(v.y));
        float rz = v.z - __bfloat162float(__float2bfloat16(v.z));
        float rw = v.w - __bfloat162float(__float2bfloat16(v.w));
        uint32_t loA0 = pkbf(rx, ry), loA1 = pkbf(rz, rw);
        uint32_t hiB0 = pkbf(wv.x, wv.y), hiB1 = pkbf(wv.z, wv.w);
        float sx = wv.x - __bfloat162float(__float2bfloat16(wv.x));
        float sy = wv.y - __bfloat162float(__float2bfloat16(wv.y));
        float sz = wv.z - __bfloat162float(__float2bfloat16(wv.z));
        float sw = wv.w - __bfloat162float(__float2bfloat16(wv.w));
        uint32_t loB0 = pkbf(sx, sy), loB1 = pkbf(sz, sw);
        uint32_t off = k * PPITCH + m4 * 8;
        *reinterpret_cast<uint2*>(psm + P_AHI + off) = make_uint2(hiA0, hiA1);
        *reinterpret_cast<uint2*>(psm + P_ALO + off) = make_uint2(loA0, loA1);
        *reinterpret_cast<uint2*>(psm + P_BHI + off) = make_uint2(hiB0, hiB1);
        *reinterpret_cast<uint2*>(psm + P_BLO + off) = make_uint2(loB0, loB1);
    }
    __syncthreads();

    const int sel = lane >> 3;
    const int lr  = lane & 7;
    const uint32_t aoff = (uint32_t)(((sel >> 1) * 8 + lr) * PPITCH + (sel & 1) * 16);
    const uint32_t boff = (uint32_t)(((sel & 1) * 8 + lr) * PPITCH + (sel >> 1) * 16);

    float acc[2][8][4] = {};

    #pragma unroll
    for (int kk = 0; kk < 8; kk++) {
        const uint32_t kb = kk * 16 * PPITCH;
        uint32_t ah[2][4], al[2][4], bh[4][4], bl[4][4];
        #pragma unroll
        for (int mf = 0; mf < 2; mf++) {
            uint32_t mcol = (wm2 * 32 + mf * 16) * 2;
            ldmx4t(ah[mf], sb + P_AHI + kb + aoff + mcol);
            ldmx4t(al[mf], sb + P_ALO + kb + aoff + mcol);
        }
        #pragma unroll
        for (int ng = 0; ng < 4; ng++) {
            uint32_t ncol = (nq2 * 64 + ng * 16) * 2;
            ldmx4t(bh[ng], sb + P_BHI + kb + boff + ncol);
            ldmx4t(bl[ng], sb + P_BLO + kb + boff + ncol);
        }
        #pragma unroll
        for (int mf = 0; mf < 2; mf++) {
            #pragma unroll
            for (int ng = 0; ng < 4; ng++) {
                float* c0 = acc[mf][ng * 2];
                float* c1 = acc[mf][ng * 2 + 1];
                mma16816(c0, ah[mf][0], ah[mf][1], ah[mf][2], ah[mf][3], bh[ng][0], bh[ng][1]);
                mma16816(c0, al[mf][0], al[mf][1], al[mf][2], al[mf][3], bh[ng][0], bh[ng][1]);
                mma16816(c0, ah[mf][0], ah[mf][1], ah[mf][2], ah[mf][3], bl[ng][0], bl[ng][1]);
                mma16816(c1, ah[mf][0], ah[mf][1], ah[mf][2], ah[mf][3], bh[ng][2], bh[ng][3]);
                mma16816(c1, al[mf][0], al[mf][1], al[mf][2], al[mf][3], bh[ng][2], bh[ng][3]);
                mma16816(c1, ah[mf][0], ah[mf][1], ah[mf][2], ah[mf][3], bl[ng][2], bl[ng][3]);
            }
        }
    }

    #pragma unroll
    for (int mf = 0; mf < 2; mf++) {
        int m = m0 + wm2 * 32 + mf * 16 + (lane >> 2);
        #pragma unroll
        for (int j = 0; j < 8; j++) {
            int hcol = hb + nq2 * 64 + j * 8 + (lane & 3) * 2;
            float2 bv = *reinterpret_cast<const float2*>(&bias[hcol]);
            int ncol = gate * 256 + hcol;
            *reinterpret_cast<float2*>(&g_gates[(size_t)m * N4 + ncol]) =
                make_float2(acc[mf][j][0] + bv.x, acc[mf][j][1] + bv.y);
            *reinterpret_cast<float2*>(&g_gates[(size_t)(m + 8) * N4 + ncol]) =
                make_float2(acc[mf][j][2] + bv.x, acc[mf][j][3] + bv.y);
        }
    }
}

// ============================ RECURRENCE ====================================
// Grid (16 nb, 8 gm) = 128 CTAs.  CTA tile: 32 batches x 64 n-cols
// (n = g*16 + hl, 16 h-cols per CTA), K = 256.
// Warps: wm = w&1 (16-batch slice), nq = w>>1 (16-n slice).  Per-warp work
// identical to the R6 champion; producers per group = 16 (was 32).
#define APITCHB 528
#define OFF_AHI 0
#define OFF_ALO (OFF_AHI + 32 * APITCHB)
#define OFF_BHI (OFF_ALO + 32 * APITCHB)
#define OFF_BLO (OFF_BHI + 64 * APITCHB)
#define OFF_CX  (OFF_BLO + 64 * APITCHB)
#define CXP 66
#define SMEM_LSTM (OFF_CX + 32 * CXP * 4)

__global__ __launch_bounds__(256, 1) void lstm_kernel(
    const float* __restrict__ Wg, const float* __restrict__ Wi,
    const float* __restrict__ Wf, const float* __restrict__ Wo)
{
    extern __shared__ char sm[];
    const uint32_t sb = smem_u32(sm);
    float* Cx = reinterpret_cast<float*>(sm + OFF_CX);

    const int tid = threadIdx.x;
    const int lane = tid & 31;
    const int w = tid >> 5;
    const int wm = w & 1;             // 16-batch slice
    const int nq = w >> 1;            // 16-n slice (0..3)
    const int nb = blockIdx.x;        // producer id in group (0..15)
    const int gm = blockIdx.y;        // batch group (0..7), 32 batches
    const int hb16 = nb * 16;

    // Build W tile bf16 hi/lo in smem once: B[n][k], n = g*16 + hl
    for (int idx = tid; idx < 64 * 256; idx += 256) {
        int k = idx >> 6;
        int n = idx & 63;
        int g = n >> 4, hl = n & 15;
        const float* W = (g == 0) ? Wg : (g == 1) ? Wi : (g == 2) ? Wf : Wo;
        float wv = W[k * H + hb16 + hl];
        __nv_bfloat16 bh = __float2bfloat16(wv);
        __nv_bfloat16 bl = __float2bfloat16(wv - __bfloat162float(bh));
        *reinterpret_cast<unsigned short*>(sm + OFF_BHI + n * APITCHB + k * 2) =
            reinterpret_cast<unsigned short&>(bh);
        *reinterpret_cast<unsigned short*>(sm + OFF_BLO + n * APITCHB + k * 2) =
            reinterpret_cast<unsigned short&>(bl);
    }
    __syncthreads();

    const uint32_t a_row = wm * 16 + (lane & 7) + ((lane >> 3) & 1) * 8;
    const uint32_t a_base = a_row * APITCHB + (lane >> 4) * 16;
    const uint32_t b_row = nq * 16 + (lane >> 4) * 8 + (lane & 7);
    const uint32_t b_base = b_row * APITCHB + ((lane >> 3) & 1) * 16;

    const int bl_ = tid >> 3;               // batch-local 0..31
    const int hl2 = (tid & 7) * 2;          // h-col pair 0..14
    const int bglob = gm * 32 + bl_;

    float2 cstate = make_float2(0.f, 0.f);

    for (int t = 0; t < T; t++) {
        // gate pre-activations (independent of h) — issue before the wait
        float2 pg, pi_, pf_, po;
        {
            const size_t rb = ((size_t)bglob * T + t) * N4 + hb16 + hl2;
            pg  = __ldcg(reinterpret_cast<const float2*>(&g_gates[rb]));
            pi_ = __ldcg(reinterpret_cast<const float2*>(&g_gates[rb + 256]));
            pf_ = __ldcg(reinterpret_cast<const float2*>(&g_gates[rb + 512]));
            po  = __ldcg(reinterpret_cast<const float2*>(&g_gates[rb + 768]));
        }

        float2 ag = make_float2(0.f, 0.f), ai = ag, af = ag, ao = ag;

        if (t > 0) {
            // warp-autonomous poll of the group counter (broadcast load/warp)
            {
                unsigned need = 16u * (unsigned)t;
                unsigned v;
                do {
                    asm volatile("ld.acquire.gpu.global.u32 %0, [%1];"
                                 : "=r"(v) : "l"(&g_bar8[gm]) : "memory");
                } while (v < need);
            }

            const unsigned short* src_hi = g_hhi[(t + 1) & 1];
            const unsigned short* src_lo = g_hlo[(t + 1) & 1];
            #pragma unroll
            for (int i = 0; i < 4; i++) {
                int idx = tid + i * 256;
                int m = idx >> 5;               // 0..31
                int ch = idx & 31;
                size_t gidx = (size_t)(gm * 32 + m) * H + ch * 8;
                uint4 vh = __ldcg(reinterpret_cast<const uint4*>(&src_hi[gidx]));
                uint4 vl = __ldcg(reinterpret_cast<const uint4*>(&src_lo[gidx]));
                *reinterpret_cast<uint4*>(sm + OFF_AHI + m * APITCHB + ch * 16) = vh;
                *reinterpret_cast<uint4*>(sm + OFF_ALO + m * APITCHB + ch * 16) = vl;
            }
            __syncthreads();                    // BAR 1: A tile staged

            float c0[4] = {0.f, 0.f, 0.f, 0.f};
            float c1[4] = {0.f, 0.f, 0.f, 0.f};
            #pragma unroll
            for (int kk = 0; kk < 16; kk++) {
                uint32_t ah[4], al[4], bh[4], blx[4];
                ldmx4(ah[0], ah[1], ah[2], ah[3], sb + OFF_AHI + a_base + kk * 32);
                ldmx4(al[0], al[1], al[2], al[3], sb + OFF_ALO + a_base + kk * 32);
                ldmx4(bh[0], bh[1], bh[2], bh[3], sb + OFF_BHI + b_base + kk * 32);
                ldmx4(blx[0], blx[1], blx[2], blx[3], sb + OFF_BLO + b_base + kk * 32);
                mma16816(c0, ah[0], ah[1], ah[2], ah[3], bh[0], bh[1]);
                mma16816(c0, al[0], al[1], al[2], al[3], bh[0], bh[1]);
                mma16816(c0, ah[0], ah[1], ah[2], ah[3], blx[0], blx[1]);
                mma16816(c1, ah[0], ah[1], ah[2], ah[3], bh[2], bh[3]);
                mma16816(c1, al[0], al[1], al[2], al[3], bh[2], bh[3]);
                mma16816(c1, ah[0], ah[1], ah[2], ah[3], blx[2], blx[3]);
            }

            {
                int crow = wm * 16 + (lane >> 2);
                int ccol = nq * 16 + (lane & 3) * 2;
                *reinterpret_cast<float2*>(&Cx[crow * CXP + ccol]) = make_float2(c0[0], c0[1]);
                *reinterpret_cast<float2*>(&Cx[(crow + 8) * CXP + ccol]) = make_float2(c0[2], c0[3]);
                *reinterpret_cast<float2*>(&Cx[crow * CXP + ccol + 8]) = make_float2(c1[0], c1[1]);
                *reinterpret_cast<float2*>(&Cx[(crow + 8) * CXP + ccol + 8]) = make_float2(c1[2], c1[3]);
            }
            __syncthreads();                    // BAR 2: C exchange ready

            ag = *reinterpret_cast<float2*>(&Cx[bl_ * CXP + 0 * 16 + hl2]);
            ai = *reinterpret_cast<float2*>(&Cx[bl_ * CXP + 1 * 16 + hl2]);
            af = *reinterpret_cast<float2*>(&Cx[bl_ * CXP + 2 * 16 + hl2]);
            ao = *reinterpret_cast<float2*>(&Cx[bl_ * CXP + 3 * 16 + hl2]);
        }

        float hx = tanf_(pg.x + ag.x);
        float hy = tanf_(pg.y + ag.y);
        float ix = sigf(pi_.x + ai.x);
        float iy = sigf(pi_.y + ai.y);
        float fx = sigf(pf_.x + af.x);
        float fy = sigf(pf_.y + af.y);
        float ox = sigf(po.x + ao.x);
        float oy = sigf(po.y + ao.y);
        cstate.x = hx * ix + cstate.x * fx;
        cstate.y = hy * iy + cstate.y * fy;
        float h0 = tanf_(cstate.x) * ox;
        float h1 = tanf_(cstate.y) * oy;

        if (t < T - 1) {
            unsigned uhi = pkbf(h0, h1);
            __nv_bfloat16 q0 = __float2bfloat16(h0);
            __nv_bfloat16 q1 = __float2bfloat16(h1);
            unsigned ulo = pkbf(h0 - __bfloat162float(q0), h1 - __bfloat162float(q1));
            size_t hidx = (size_t)bglob * H + hb16 + hl2;
            __stcg(reinterpret_cast<unsigned*>(&g_hhi[t & 1][hidx]), uhi);
            __stcg(reinterpret_cast<unsigned*>(&g_hlo[t & 1][hidx]), ulo);
            __syncthreads();                    // BAR 3: all h stores issued
            if (tid == 0) {
                asm volatile("red.release.gpu.global.add.u32 [%0], %1;"
                             :: "l"(&g_bar8[gm]), "r"(1u) : "memory");
            }
        } else {
            *reinterpret_cast<float2*>(&g_hfin[(size_t)bglob * H + hb16 + hl2]) =
                make_float2(h0, h1);
        }
    }
}

// ================================ HEAD ======================================
__global__ void final_kernel(const float* __restrict__ Wp,
                             const float* __restrict__ bp,
                             float* __restrict__ out)
{
    __shared__ float hsm[H];
    int b = blockIdx.x;
    hsm[threadIdx.x] = g_hfin[b * H + threadIdx.x];
    __syncthreads();
    if (threadIdx.x < C) {
        float acc = bp[threadIdx.x];
        #pragma unroll 8
        for (int k = 0; k < H; k++)
            acc += hsm[k] * Wp[k * C + threadIdx.x];
        out[b * C + threadIdx.x] = acc;
    }
}

// ---------------------------------------------------------------------------
extern "C" void kernel_launch(void* const* d_in, const int* in_sizes, int n_in,
                              void* d_out, int out_size)
{
    const float* x    = (const float*)d_in[0];
    const float* W_gx = (const float*)d_in[1];
    const float* W_ix = (const float*)d_in[2];
    const float* W_fx = (const float*)d_in[3];
    const float* W_ox = (const float*)d_in[4];
    const float* W_gh = (const float*)d_in[5];
    const float* W_ih = (const float*)d_in[6];
    const float* W_fh = (const float*)d_in[7];
    const float* W_oh = (const float*)d_in[8];
    const float* b_g  = (const float*)d_in[9];
    const float* b_i  = (const float*)d_in[10];
    const float* b_f  = (const float*)d_in[11];
    const float* b_o  = (const float*)d_in[12];
    const float* W_ph = (const float*)d_in[13];
    const float* b_p  = (const float*)d_in[14];
    float* out = (float*)d_out;

    static bool attr_set = false;
    if (!attr_set) {
        cudaFuncSetAttribute(lstm_kernel,
                             cudaFuncAttributeMaxDynamicSharedMemorySize, SMEM_LSTM);
        cudaFuncSetAttribute(projmma_kernel,
                             cudaFuncAttributeMaxDynamicSharedMemorySize, SMEM_PROJ);
        attr_set = true;
    }

    reset_kernel<<<1, 32>>>();

    projmma_kernel<<<dim3(N4 / 128, (B * T) / 128), 256, SMEM_PROJ>>>(
        x, W_gx, W_ix, W_fx, W_ox, b_g, b_i, b_f, b_o);

    lstm_kernel<<<dim3(16, 8), 256, SMEM_LSTM>>>(W_gh, W_ih, W_fh, W_oh);

    final_kernel<<<B, H>>>(W_ph, b_p, out);
}

// round 16
// speedup vs baseline: 1.7407x; 1.0145x over previous
#include <cuda_runtime.h>
#include <cuda_bf16.h>
#include <math.h>
#include <stdint.h>

#define B 256
#define D 128
#define T 512
#define H 256
#define C 10
#define N4 1024

// device scratch (no runtime allocation allowed)
__device__ float g_gates[(size_t)B * T * N4];        // [b][t][4H] fp32, 512 MB
__device__ unsigned short g_hhi[2][B * H];           // h bf16 hi, [b][k], dbl-buffered
__device__ unsigned short g_hlo[2][B * H];           // h bf16 lo
__device__ float g_hfin[B * H];                      // final h fp32
__device__ unsigned g_bar16[16];                     // per-group step counters

// fast activations: __expf-based (rel err ~1e-6, saturating, no NaN)
__device__ __forceinline__ float sigf(float x) { return 1.0f / (1.0f + __expf(-x)); }
__device__ __forceinline__ float tanf_(float x) {
    float e = __expf(2.0f * x);
    return 1.0f - 2.0f / (e + 1.0f);
}

__global__ void reset_kernel() {
    if (threadIdx.x < 16) g_bar16[threadIdx.x] = 0u;
}

__device__ __forceinline__ uint32_t smem_u32(const void* p) {
    uint32_t a;
    asm("{ .reg .u64 t; cvta.to.shared.u64 t, %1; cvt.u32.u64 %0, t; }" : "=r"(a) : "l"(p));
    return a;
}
__device__ __forceinline__ void ldmx4(uint32_t& r0, uint32_t& r1, uint32_t& r2,
                                      uint32_t& r3, uint32_t addr) {
    asm volatile("ldmatrix.sync.aligned.m8n8.x4.shared.b16 {%0,%1,%2,%3}, [%4];"
                 : "=r"(r0), "=r"(r1), "=r"(r2), "=r"(r3) : "r"(addr));
}
__device__ __forceinline__ void ldmx4t(uint32_t* r, uint32_t addr) {
    asm volatile("ldmatrix.sync.aligned.m8n8.x4.trans.shared.b16 {%0,%1,%2,%3}, [%4];"
                 : "=r"(r[0]), "=r"(r[1]), "=r"(r[2]), "=r"(r[3]) : "r"(addr));
}
__device__ __forceinline__ void mma16816(float* c,
                                         uint32_t a0, uint32_t a1, uint32_t a2, uint32_t a3,
                                         uint32_t b0, uint32_t b1) {
    asm volatile(
        "mma.sync.aligned.m16n8k16.row.col.f32.bf16.bf16.f32 "
        "{%0,%1,%2,%3}, {%4,%5,%6,%7}, {%8,%9}, {%0,%1,%2,%3};"
        : "+f"(c[0]), "+f"(c[1]), "+f"(c[2]), "+f"(c[3])
        : "r"(a0), "r"(a1), "r"(a2), "r"(a3), "r"(b0), "r"(b1));
}
__device__ __forceinline__ uint32_t pkbf(float x, float y) {
    __nv_bfloat16 a = __float2bfloat16(x), b = __float2bfloat16(y);
    return (uint32_t)reinterpret_cast<unsigned short&>(a) |
           ((uint32_t)reinterpret_cast<unsigned short&>(b) << 16);
}

// ============================== PROJ (mma) ==================================
#define PPITCH 272
#define P_AHI 0
#define P_ALO (128 * PPITCH)
#define P_BHI (2 * 128 * PPITCH)
#define P_BLO (3 * 128 * PPITCH)
#define SMEM_PROJ (4 * 128 * PPITCH)

__global__ __launch_bounds__(256, 1) void projmma_kernel(
    const float* __restrict__ x,
    const float* __restrict__ Wg, const float* __restrict__ Wi,
    const float* __restrict__ Wf, const float* __restrict__ Wo,
    const float* __restrict__ bg, const float* __restrict__ bi,
    const float* __restrict__ bf, const float* __restrict__ bo)
{
    extern __shared__ char psm[];
    const uint32_t sb = smem_u32(psm);

    const int tid = threadIdx.x;
    const int lane = tid & 31;
    const int w = tid >> 5;
    const int wm2 = w & 3;
    const int nq2 = w >> 2;
    const int n0 = blockIdx.x * 128;
    const int m0 = blockIdx.y * 128;
    const int b  = m0 >> 9;
    const int t0 = m0 & 511;
    const int gate = n0 >> 8;
    const int hb = n0 & 255;

    const float* W    = (gate == 0) ? Wg : (gate == 1) ? Wi : (gate == 2) ? Wf : Wo;
    const float* bias = (gate == 0) ? bg : (gate == 1) ? bi : (gate == 2) ? bf : bo;

    #pragma unroll
    for (int i = 0; i < 16; i++) {
        int q = tid + i * 256;
        int k = q >> 5;
        int m4 = q & 31;
        float4 v = __ldcg(reinterpret_cast<const float4*>(
            &x[(size_t)b * (D * T) + k * T + t0 + m4 * 4]));
        float4 wv = __ldg(reinterpret_cast<const float4*>(&W[k * H + hb + m4 * 4]));
        uint32_t hiA0 = pkbf(v.x, v.y), hiA1 = pkbf(v.z, v.w);
        float rx = v.x - __bfloat162float(__float2bfloat16(v.x));
        float ry = v.y - __bfloat162float(__float2bfloat16(v.y));
        float rz = v.z - __bfloat162float(__float2bfloat16(v.z));
        float rw = v.w - __bfloat162float(__float2bfloat16(v.w));
        uint32_t loA0 = pkbf(rx, ry), loA1 = pkbf(rz, rw);
        uint32_t hiB0 = pkbf(wv.x, wv.y), hiB1 = pkbf(wv.z, wv.w);
        float sx = wv.x - __bfloat162float(__float2bfloat16(wv.x));
        float sy = wv.y - __bfloat162float(__float2bfloat16(wv.y));
        float sz = wv.z - __bfloat162float(__float2bfloat16(wv.z));
        float sw = wv.w - __bfloat162float(__float2bfloat16(wv.w));
        uint32_t loB0 = pkbf(sx, sy), loB1 = pkbf(sz, sw);
        uint32_t off = k * PPITCH + m4 * 8;
        *reinterpret_cast<uint2*>(psm + P_AHI + off) = make_uint2(hiA0, hiA1);
        *reinterpret_cast<uint2*>(psm + P_ALO + off) = make_uint2(loA0, loA1);
        *reinterpret_cast<uint2*>(psm + P_BHI + off) = make_uint2(hiB0, hiB1);
        *reinterpret_cast<uint2*>(psm + P_BLO + off) = make_uint2(loB0, loB1);
    }
    __syncthreads();

    const int sel = lane >> 3;
    const int lr  = lane & 7;
    const uint32_t aoff = (uint32_t)(((sel >> 1) * 8 + lr) * PPITCH + (sel & 1) * 16);
    const uint32_t boff = (uint32_t)(((sel & 1) * 8 + lr) * PPITCH + (sel >> 1) * 16);

    float acc[2][8][4] = {};

    #pragma unroll
    for (int kk = 0; kk < 8; kk++) {
        const uint32_t kb = kk * 16 * PPITCH;
        uint32_t ah[2][4], al[2][4], bh[4][4], bl[4][4];
        #pragma unroll
        for (int mf = 0; mf < 2; mf++) {
            uint32_t mcol = (wm2 * 32 + mf * 16) * 2;
            ldmx4t(ah[mf], sb + P_AHI + kb + aoff + mcol);
            ldmx4t(al[mf], sb + P_ALO + kb + aoff + mcol);
        }
        #pragma unroll
        for (int ng = 0; ng < 4; ng++) {
            uint32_t ncol = (nq2 * 64 + ng * 16) * 2;
            ldmx4t(bh[ng], sb + P_BHI + kb + boff + ncol);
            ldmx4t(bl[ng], sb + P_BLO + kb + boff + ncol);
        }
        #pragma unroll
        for (int mf = 0; mf < 2; mf++) {
            #pragma unroll
            for (int ng = 0; ng < 4; ng++) {
                float* c0 = acc[mf][ng * 2];
                float* c1 = acc[mf][ng * 2 + 1];
                mma16816(c0, ah[mf][0], ah[mf][1], ah[mf][2], ah[mf][3], bh[ng][0], bh[ng][1]);
                mma16816(c0, al[mf][0], al[mf][1], al[mf][2], al[mf][3], bh[ng][0], bh[ng][1]);
                mma16816(c0, ah[mf][0], ah[mf][1], ah[mf][2], ah[mf][3], bl[ng][0], bl[ng][1]);
                mma16816(c1, ah[mf][0], ah[mf][1], ah[mf][2], ah[mf][3], bh[ng][2], bh[ng][3]);
                mma16816(c1, al[mf][0], al[mf][1], al[mf][2], al[mf][3], bh[ng][2], bh[ng][3]);
                mma16816(c1, ah[mf][0], ah[mf][1], ah[mf][2], ah[mf][3], bl[ng][2], bl[ng][3]);
            }
        }
    }

    #pragma unroll
    for (int mf = 0; mf < 2; mf++) {
        int m = m0 + wm2 * 32 + mf * 16 + (lane >> 2);
        #pragma unroll
        for (int j = 0; j < 8; j++) {
            int hcol = hb + nq2 * 64 + j * 8 + (lane & 3) * 2;
            float2 bv = *reinterpret_cast<const float2*>(&bias[hcol]);
            int ncol = gate * 256 + hcol;
            *reinterpret_cast<float2*>(&g_gates[(size_t)m * N4 + ncol]) =
                make_float2(acc[mf][j][0] + bv.x, acc[mf][j][1] + bv.y);
            *reinterpret_cast<float2*>(&g_gates[(size_t)(m + 8) * N4 + ncol]) =
                make_float2(acc[mf][j][2] + bv.x, acc[mf][j][3] + bv.y);
        }
    }
}

// ============================ RECURRENCE ====================================
// Grid (8 nb, 16 gm) = 128 CTAs.  CTA tile: 16 batches x 128 n-cols
// (n = g*32 + hl, 32 h-cols per CTA), K = 256.
// Warps: all 8 share the single m16 (16 batches); nq = w (16-n slice).
// Producers per group = 8 (was 16).
#define APITCHB 528
#define OFF_AHI 0
#define OFF_ALO (OFF_AHI + 16 * APITCHB)
#define OFF_BHI (OFF_ALO + 16 * APITCHB)
#define OFF_BLO (OFF_BHI + 128 * APITCHB)
#define OFF_CX  (OFF_BLO + 128 * APITCHB)
#define CXP 130
#define SMEM_LSTM (OFF_CX + 16 * CXP * 4)     // 160384 B

__global__ __launch_bounds__(256, 1) void lstm_kernel(
    const float* __restrict__ Wg, const float* __restrict__ Wi,
    const float* __restrict__ Wf, const float* __restrict__ Wo)
{
    extern __shared__ char sm[];
    const uint32_t sb = smem_u32(sm);
    float* Cx = reinterpret_cast<float*>(sm + OFF_CX);

    const int tid = threadIdx.x;
    const int lane = tid & 31;
    const int nq = tid >> 5;          // warp id = 16-n slice (0..7)
    const int nb = blockIdx.x;        // producer id in group (0..7)
    const int gm = blockIdx.y;        // batch group (0..15), 16 batches
    const int hb32 = nb * 32;

    // Build W tile bf16 hi/lo in smem once: B[n][k], n = g*32 + hl
    for (int idx = tid; idx < 128 * 256; idx += 256) {
        int k = idx >> 7;
        int n = idx & 127;
        int g = n >> 5, hl = n & 31;
        const float* W = (g == 0) ? Wg : (g == 1) ? Wi : (g == 2) ? Wf : Wo;
        float wv = W[k * H + hb32 + hl];
        __nv_bfloat16 bh = __float2bfloat16(wv);
        __nv_bfloat16 bl = __float2bfloat16(wv - __bfloat162float(bh));
        *reinterpret_cast<unsigned short*>(sm + OFF_BHI + n * APITCHB + k * 2) =
            reinterpret_cast<unsigned short&>(bh);
        *reinterpret_cast<unsigned short*>(sm + OFF_BLO + n * APITCHB + k * 2) =
            reinterpret_cast<unsigned short&>(bl);
    }
    __syncthreads();

    // A fragment (all warps identical; smem broadcast is free)
    const uint32_t a_row = (lane & 7) + ((lane >> 3) & 1) * 8;
    const uint32_t a_base = a_row * APITCHB + (lane >> 4) * 16;
    const uint32_t b_row = nq * 16 + (lane >> 4) * 8 + (lane & 7);
    const uint32_t b_base = b_row * APITCHB + ((lane >> 3) & 1) * 16;

    const int bl_ = tid >> 4;               // batch-local 0..15
    const int hl2 = (tid & 15) * 2;         // h-col pair 0..30
    const int bglob = gm * 16 + bl_;

    float2 cstate = make_float2(0.f, 0.f);

    for (int t = 0; t < T; t++) {
        // gate pre-activations (independent of h) — issue before the wait
        float2 pg, pi_, pf_, po;
        {
            const size_t rb = ((size_t)bglob * T + t) * N4 + hb32 + hl2;
            pg  = __ldcg(reinterpret_cast<const float2*>(&g_gates[rb]));
            pi_ = __ldcg(reinterpret_cast<const float2*>(&g_gates[rb + 256]));
            pf_ = __ldcg(reinterpret_cast<const float2*>(&g_gates[rb + 512]));
            po  = __ldcg(reinterpret_cast<const float2*>(&g_gates[rb + 768]));
        }

        float2 ag = make_float2(0.f, 0.f), ai = ag, af = ag, ao = ag;

        if (t > 0) {
            // warp-autonomous poll of the group counter (broadcast load/warp)
            {
                unsigned need = 8u * (unsigned)t;
                unsigned v;
                do {
                    asm volatile("ld.acquire.gpu.global.u32 %0, [%1];"
                                 : "=r"(v) : "l"(&g_bar16[gm]) : "memory");
                } while (v < need);
            }

            const unsigned short* src_hi = g_hhi[(t + 1) & 1];
            const unsigned short* src_lo = g_hlo[(t + 1) & 1];
            #pragma unroll
            for (int i = 0; i < 2; i++) {
                int idx = tid + i * 256;
                int m = idx >> 5;               // 0..15
                int ch = idx & 31;
                size_t gidx = (size_t)(gm * 16 + m) * H + ch * 8;
                uint4 vh = __ldcg(reinterpret_cast<const uint4*>(&src_hi[gidx]));
                uint4 vl = __ldcg(reinterpret_cast<const uint4*>(&src_lo[gidx]));
                *reinterpret_cast<uint4*>(sm + OFF_AHI + m * APITCHB + ch * 16) = vh;
                *reinterpret_cast<uint4*>(sm + OFF_ALO + m * APITCHB + ch * 16) = vl;
            }
            __syncthreads();                    // BAR 1: A tile staged

            float c0[4] = {0.f, 0.f, 0.f, 0.f};
            float c1[4] = {0.f, 0.f, 0.f, 0.f};
            #pragma unroll
            for (int kk = 0; kk < 16; kk++) {
                uint32_t ah[4], al[4], bh[4], blx[4];
                ldmx4(ah[0], ah[1], ah[2], ah[3], sb + OFF_AHI + a_base + kk * 32);
                ldmx4(al[0], al[1], al[2], al[3], sb + OFF_ALO + a_base + kk * 32);
                ldmx4(bh[0], bh[1], bh[2], bh[3], sb + OFF_BHI + b_base + kk * 32);
                ldmx4(blx[0], blx[1], blx[2], blx[3], sb + OFF_BLO + b_base + kk * 32);
                mma16816(c0, ah[0], ah[1], ah[2], ah[3], bh[0], bh[1]);
                mma16816(c0, al[0], al[1], al[2], al[3], bh[0], bh[1]);
                mma16816(c0, ah[0], ah[1], ah[2], ah[3], blx[0], blx[1]);
                mma16816(c1, ah[0], ah[1], ah[2], ah[3], bh[2], bh[3]);
                mma16816(c1, al[0], al[1], al[2], al[3], bh[2], bh[3]);
                mma16816(c1, ah[0], ah[1], ah[2], ah[3], blx[2], blx[3]);
            }

            {
                int crow = lane >> 2;                   // 0..7
                int ccol = nq * 16 + (lane & 3) * 2;
                *reinterpret_cast<float2*>(&Cx[crow * CXP + ccol]) = make_float2(c0[0], c0[1]);
                *reinterpret_cast<float2*>(&Cx[(crow + 8) * CXP + ccol]) = make_float2(c0[2], c0[3]);
                *reinterpret_cast<float2*>(&Cx[crow * CXP + ccol + 8]) = make_float2(c1[0], c1[1]);
                *reinterpret_cast<float2*>(&Cx[(crow + 8) * CXP + ccol + 8]) = make_float2(c1[2], c1[3]);
            }
            __syncthreads();                    // BAR 2: C exchange ready

            ag = *reinterpret_cast<float2*>(&Cx[bl_ * CXP + 0 * 32 + hl2]);
            ai = *reinterpret_cast<float2*>(&Cx[bl_ * CXP + 1 * 32 + hl2]);
            af = *reinterpret_cast<float2*>(&Cx[bl_ * CXP + 2 * 32 + hl2]);
            ao = *reinterpret_cast<float2*>(&Cx[bl_ * CXP + 3 * 32 + hl2]);
        }

        float hx = tanf_(pg.x + ag.x);
        float hy = tanf_(pg.y + ag.y);
        float ix = sigf(pi_.x + ai.x);
        float iy = sigf(pi_.y + ai.y);
        float fx = sigf(pf_.x + af.x);
        float fy = sigf(pf_.y + af.y);
        float ox = sigf(po.x + ao.x);
        float oy = sigf(po.y + ao.y);
        cstate.x = hx * ix + cstate.x * fx;
        cstate.y = hy * iy + cstate.y * fy;
        float h0 = tanf_(cstate.x) * ox;
        float h1 = tanf_(cstate.y) * oy;

        if (t < T - 1) {
            unsigned uhi = pkbf(h0, h1);
            __nv_bfloat16 q0 = __float2bfloat16(h0);
            __nv_bfloat16 q1 = __float2bfloat16(h1);
            unsigned ulo = pkbf(h0 - __bfloat162float(q0), h1 - __bfloat162float(q1));
            size_t hidx = (size_t)bglob * H + hb32 + hl2;
            __stcg(reinterpret_cast<unsigned*>(&g_hhi[t & 1][hidx]), uhi);
            __stcg(reinterpret_cast<unsigned*>(&g_hlo[t & 1][hidx]), ulo);
            __syncthreads();                    // BAR 3: all h stores issued
            if (tid == 0) {
                asm volatile("red.release.gpu.global.add.u32 [%0], %1;"
                             :: "l"(&g_bar16[gm]), "r"(1u) : "memory");
            }
        } else {
            *reinterpret_cast<float2*>(&g_hfin[(size_t)bglob * H + hb32 + hl2]) =
                make_float2(h0, h1);
        }
    }
}

// ================================ HEAD ======================================
__global__ void final_kernel(const float* __restrict__ Wp,
                             const float* __restrict__ bp,
                             float* __restrict__ out)
{
    __shared__ float hsm[H];
    int b = blockIdx.x;
    hsm[threadIdx.x] = g_hfin[b * H + threadIdx.x];
    __syncthreads();
    if (threadIdx.x < C) {
        float acc = bp[threadIdx.x];
        #pragma unroll 8
        for (int k = 0; k < H; k++)
            acc += hsm[k] * Wp[k * C + threadIdx.x];
        out[b * C + threadIdx.x] = acc;
    }
}

// ---------------------------------------------------------------------------
extern "C" void kernel_launch(void* const* d_in, const int* in_sizes, int n_in,
                              void* d_out, int out_size)
{
    const float* x    = (const float*)d_in[0];
    const float* W_gx = (const float*)d_in[1];
    const float* W_ix = (const float*)d_in[2];
    const float* W_fx = (const float*)d_in[3];
    const float* W_ox = (const float*)d_in[4];
    const float* W_gh = (const float*)d_in[5];
    const float* W_ih = (const float*)d_in[6];
    const float* W_fh = (const float*)d_in[7];
    const float* W_oh = (const float*)d_in[8];
    const float* b_g  = (const float*)d_in[9];
    const float* b_i  = (const float*)d_in[10];
    const float* b_f  = (const float*)d_in[11];
    const float* b_o  = (const float*)d_in[12];
    const float* W_ph = (const float*)d_in[13];
    const float* b_p  = (const float*)d_in[14];
    float* out = (float*)d_out;

    static bool attr_set = false;
    if (!attr_set) {
        cudaFuncSetAttribute(lstm_kernel,
                             cudaFuncAttributeMaxDynamicSharedMemorySize, SMEM_LSTM);
        cudaFuncSetAttribute(projmma_kernel,
                             cudaFuncAttributeMaxDynamicSharedMemorySize, SMEM_PROJ);
        attr_set = true;
    }

    reset_kernel<<<1, 32>>>();

    projmma_kernel<<<dim3(N4 / 128, (B * T) / 128), 256, SMEM_PROJ>>>(
        x, W_gx, W_ix, W_fx, W_ox, b_g, b_i, b_f, b_o);

    lstm_kernel<<<dim3(8, 16), 256, SMEM_LSTM>>>(W_gh, W_ih, W_fh, W_oh);

    final_kernel<<<B, H>>>(W_ph, b_p, out);
}